// round 15
// baseline (speedup 1.0000x reference)
#include <cuda_runtime.h>

#define IMG_H 512
#define IMG_W 512
#define NIMG  16
#define TW    32
#define TH    32
#define RH    42            // TH + 10 halo rows of hblur
#define HSTR  34            // hblur u64 stride (even -> 16B-aligned px pairs)
#define NPIX  (NIMG * IMG_H * IMG_W)
#define NBLK  (NIMG * (IMG_H / TH) * (IMG_W / TW))   // 4096

typedef unsigned long long u64;

__device__ float        g_part[NBLK];
__device__ unsigned int g_count;     // zero-init at load; reset by last block

// ---- packed f32x2 helpers (sm_100+; ptxas never emits these from C++) ----
__device__ __forceinline__ u64 pk(float lo, float hi) {
    u64 r; asm("mov.b64 %0, {%1, %2};" : "=l"(r) : "f"(lo), "f"(hi)); return r;
}
__device__ __forceinline__ void upk(float& lo, float& hi, u64 v) {
    asm("mov.b64 {%0, %1}, %2;" : "=f"(lo), "=f"(hi) : "l"(v));
}
__device__ __forceinline__ u64 fma2(u64 a, u64 b, u64 c) {
    u64 d; asm("fma.rn.f32x2 %0, %1, %2, %3;" : "=l"(d) : "l"(a), "l"(b), "l"(c)); return d;
}

__global__ void __launch_bounds__(256, 4) ssim_kernel(
    const float* __restrict__ fused,
    const float* __restrict__ imga,
    const float* __restrict__ imgb,
    float* __restrict__ out)
{
    extern __shared__ u64 smem[];
    u64* hb0 = smem;                       // [RH][HSTR] packed (muF, muA)
    u64* hb1 = hb0 + RH * HSTR;            // (muB, eF2)
    u64* hb2 = hb1 + RH * HSTR;            // (eA2, eB2)
    u64* hb3 = hb2 + RH * HSTR;            // (eFA, eFB)

    constexpr float GW[11] = {
        0.00102838f, 0.00759876f, 0.03600077f, 0.10936069f, 0.21300553f,
        0.26601172f,
        0.21300553f, 0.10936069f, 0.03600077f, 0.00759876f, 0.00102838f};
    const float c1 = 0.0001f;
    const float c2 = 0.0009f;

    const int tid = threadIdx.x;
    const int bx  = blockIdx.x;
    const int gy0 = blockIdx.y * TH - 5;
    const size_t base = (size_t)blockIdx.z * (IMG_H * IMG_W);
    const float* fP = fused + base;
    const float* aP = imga + base;
    const float* bP = imgb + base;
    const bool edge_x = (bx == 0) | (bx == (IMG_W / TW) - 1);

    // ---- Stage 1 / pass 1: rows 0..31, 4 outputs/thread (tasks 0..255) ----
    {
        const int y  = tid >> 3;            // 0..31
        const int x0 = (tid & 7) * 4;
        const int gy = gy0 + y;

        float acc[4][8];
#pragma unroll
        for (int j = 0; j < 4; j++)
#pragma unroll
            for (int c = 0; c < 8; c++) acc[j][c] = 0.f;

        if (gy >= 0 && gy < IMG_H) {
            if (!edge_x) {
                const int gxa = bx * TW + x0 - 8;       // multiple of 4, >=24
                const float4* f4 = (const float4*)(fP + gy * IMG_W + gxa);
                const float4* a4 = (const float4*)(aP + gy * IMG_W + gxa);
                const float4* b4 = (const float4*)(bP + gy * IMG_W + gxa);
#pragma unroll
                for (int q = 0; q < 5; q++) {
                    float4 fv = f4[q], av = a4[q], bv = b4[q];
                    float fs[4] = {fv.x, fv.y, fv.z, fv.w};
                    float as[4] = {av.x, av.y, av.z, av.w};
                    float bs[4] = {bv.x, bv.y, bv.z, bv.w};
#pragma unroll
                    for (int m = 0; m < 4; m++) {
                        int k = q * 4 + m - 3;          // window px 0..13
                        if (k < 0 || k >= 14) continue;
                        float f = fmaf(fs[m], 0.5f, 0.5f);
                        float a = fmaf(as[m], 0.5f, 0.5f);
                        float b = fmaf(bs[m], 0.5f, 0.5f);
                        float v[8] = {f, a, b, f * f, a * a, b * b,
                                      f * a, f * b};
#pragma unroll
                        for (int j = 0; j < 4; j++) {
                            int tt = k - j;             // compile-time
                            if (tt >= 0 && tt < 11) {
#pragma unroll
                                for (int c = 0; c < 8; c++)
                                    acc[j][c] = fmaf(v[c], GW[tt], acc[j][c]);
                            }
                        }
                    }
                }
            } else {
                const int gxw = bx * TW + x0 - 5;
                const float* frow = fP + gy * IMG_W;
                const float* arow = aP + gy * IMG_W;
                const float* brow = bP + gy * IMG_W;
#pragma unroll
                for (int k = 0; k < 14; k++) {
                    int gx = gxw + k;
                    float f = 0.f, a = 0.f, b = 0.f;
                    if (gx >= 0 && gx < IMG_W) {
                        f = fmaf(frow[gx], 0.5f, 0.5f);
                        a = fmaf(arow[gx], 0.5f, 0.5f);
                        b = fmaf(brow[gx], 0.5f, 0.5f);
                    }
                    float v[8] = {f, a, b, f * f, a * a, b * b, f * a, f * b};
#pragma unroll
                    for (int j = 0; j < 4; j++) {
                        int tt = k - j;
                        if (tt >= 0 && tt < 11) {
#pragma unroll
                            for (int c = 0; c < 8; c++)
                                acc[j][c] = fmaf(v[c], GW[tt], acc[j][c]);
                        }
                    }
                }
            }
        }

        const int o = y * HSTR + x0;        // even -> 16B aligned
        ((ulonglong2*)(hb0 + o))[0] = make_ulonglong2(pk(acc[0][0], acc[0][1]), pk(acc[1][0], acc[1][1]));
        ((ulonglong2*)(hb0 + o))[1] = make_ulonglong2(pk(acc[2][0], acc[2][1]), pk(acc[3][0], acc[3][1]));
        ((ulonglong2*)(hb1 + o))[0] = make_ulonglong2(pk(acc[0][2], acc[0][3]), pk(acc[1][2], acc[1][3]));
        ((ulonglong2*)(hb1 + o))[1] = make_ulonglong2(pk(acc[2][2], acc[2][3]), pk(acc[3][2], acc[3][3]));
        ((ulonglong2*)(hb2 + o))[0] = make_ulonglong2(pk(acc[0][4], acc[0][5]), pk(acc[1][4], acc[1][5]));
        ((ulonglong2*)(hb2 + o))[1] = make_ulonglong2(pk(acc[2][4], acc[2][5]), pk(acc[3][4], acc[3][5]));
        ((ulonglong2*)(hb3 + o))[0] = make_ulonglong2(pk(acc[0][6], acc[0][7]), pk(acc[1][6], acc[1][7]));
        ((ulonglong2*)(hb3 + o))[1] = make_ulonglong2(pk(acc[2][6], acc[2][7]), pk(acc[3][6], acc[3][7]));
    }

    // ---- Stage 1 / pass 2: rows 32..41 as 160 HALF tasks (2 outputs) ----
    // Splits R6's 80 leftover full tasks across 160 threads: critical path
    // per thread drops from 2 full tasks to 1 full + 1 half.
    if (tid < 160) {
        const int y  = 32 + (tid >> 4);     // 32..41
        const int x0 = (tid & 15) * 2;      // even
        const int gy = gy0 + y;

        float acc[2][8];
#pragma unroll
        for (int j = 0; j < 2; j++)
#pragma unroll
            for (int c = 0; c < 8; c++) acc[j][c] = 0.f;

        if (gy >= 0 && gy < IMG_H) {
            if (!edge_x) {
                // window px k=0..11 -> gx = bx*32 + x0 - 5 + k
                // aligned float2 base: gx = bx*32 + x0 - 6 (even); m=1..12
                const int gxa = bx * TW + x0 - 6;
                const float2* f2 = (const float2*)(fP + gy * IMG_W + gxa);
                const float2* a2 = (const float2*)(aP + gy * IMG_W + gxa);
                const float2* b2 = (const float2*)(bP + gy * IMG_W + gxa);
#pragma unroll
                for (int q = 0; q < 7; q++) {
                    float2 fv = f2[q], av = a2[q], bv = b2[q];
                    float fs[2] = {fv.x, fv.y};
                    float as[2] = {av.x, av.y};
                    float bs[2] = {bv.x, bv.y};
#pragma unroll
                    for (int m = 0; m < 2; m++) {
                        int k = q * 2 + m - 1;          // window px 0..11
                        if (k < 0 || k >= 12) continue;
                        float f = fmaf(fs[m], 0.5f, 0.5f);
                        float a = fmaf(as[m], 0.5f, 0.5f);
                        float b = fmaf(bs[m], 0.5f, 0.5f);
                        float v[8] = {f, a, b, f * f, a * a, b * b,
                                      f * a, f * b};
#pragma unroll
                        for (int j = 0; j < 2; j++) {
                            int tt = k - j;             // compile-time
                            if (tt >= 0 && tt < 11) {
#pragma unroll
                                for (int c = 0; c < 8; c++)
                                    acc[j][c] = fmaf(v[c], GW[tt], acc[j][c]);
                            }
                        }
                    }
                }
            } else {
                const int gxw = bx * TW + x0 - 5;
                const float* frow = fP + gy * IMG_W;
                const float* arow = aP + gy * IMG_W;
                const float* brow = bP + gy * IMG_W;
#pragma unroll
                for (int k = 0; k < 12; k++) {
                    int gx = gxw + k;
                    float f = 0.f, a = 0.f, b = 0.f;
                    if (gx >= 0 && gx < IMG_W) {
                        f = fmaf(frow[gx], 0.5f, 0.5f);
                        a = fmaf(arow[gx], 0.5f, 0.5f);
                        b = fmaf(brow[gx], 0.5f, 0.5f);
                    }
                    float v[8] = {f, a, b, f * f, a * a, b * b, f * a, f * b};
#pragma unroll
                    for (int j = 0; j < 2; j++) {
                        int tt = k - j;
                        if (tt >= 0 && tt < 11) {
#pragma unroll
                            for (int c = 0; c < 8; c++)
                                acc[j][c] = fmaf(v[c], GW[tt], acc[j][c]);
                        }
                    }
                }
            }
        }

        const int o = y * HSTR + x0;        // even -> 16B aligned
        *(ulonglong2*)(hb0 + o) = make_ulonglong2(pk(acc[0][0], acc[0][1]), pk(acc[1][0], acc[1][1]));
        *(ulonglong2*)(hb1 + o) = make_ulonglong2(pk(acc[0][2], acc[0][3]), pk(acc[1][2], acc[1][3]));
        *(ulonglong2*)(hb2 + o) = make_ulonglong2(pk(acc[0][4], acc[0][5]), pk(acc[1][4], acc[1][5]));
        *(ulonglong2*)(hb3 + o) = make_ulonglong2(pk(acc[0][6], acc[0][7]), pk(acc[1][6], acc[1][7]));
    }
    __syncthreads();

    // ---- Stage 2: vertical blur (4 outputs/thread) + SSIM ----
    float lsum = 0.f;
    {
        const int x  = tid & 31;
        const int yb = (tid >> 5) * 4;

        u64 acc[4][4];
#pragma unroll
        for (int j = 0; j < 4; j++)
#pragma unroll
            for (int c = 0; c < 4; c++) acc[j][c] = 0ull;

#pragma unroll
        for (int r = 0; r < 14; r++) {
            int o = (yb + r) * HSTR + x;
            u64 q0 = hb0[o], q1 = hb1[o], q2 = hb2[o], q3 = hb3[o];
#pragma unroll
            for (int j = 0; j < 4; j++) {
                int tt = r - j;
                if (tt >= 0 && tt < 11) {
                    u64 w = pk(GW[tt], GW[tt]);     // imm pair, remat-friendly
                    acc[j][0] = fma2(q0, w, acc[j][0]);
                    acc[j][1] = fma2(q1, w, acc[j][1]);
                    acc[j][2] = fma2(q2, w, acc[j][2]);
                    acc[j][3] = fma2(q3, w, acc[j][3]);
                }
            }
        }

#pragma unroll
        for (int j = 0; j < 4; j++) {
            float muF, muA, muB, eF2, eA2, eB2, eFA, eFB;
            upk(muF, muA, acc[j][0]);
            upk(muB, eF2, acc[j][1]);
            upk(eA2, eB2, acc[j][2]);
            upk(eFA, eFB, acc[j][3]);
            float muF2 = muF * muF;
            float sF2  = eF2 - muF2;
            float muA2 = muA * muA;
            float m12a = muF * muA;
            float sA2  = eA2 - muA2;
            float s12a = eFA - m12a;
            float na   = (2.f * m12a + c1) * (2.f * s12a + c2);
            float da   = (muF2 + muA2 + c1) * (sF2 + sA2 + c2);
            float muB2 = muB * muB;
            float m12b = muF * muB;
            float sB2  = eB2 - muB2;
            float s12b = eFB - m12b;
            float nb   = (2.f * m12b + c1) * (2.f * s12b + c2);
            float db   = (muF2 + muB2 + c1) * (sF2 + sB2 + c2);
            float num = fmaf(na, db, nb * da);
            lsum += __fdividef(num, da * db);
        }
    }

    // ---- Block reduction -> deterministic per-block partial ----
#pragma unroll
    for (int o = 16; o > 0; o >>= 1)
        lsum += __shfl_down_sync(0xffffffffu, lsum, o);

    __shared__ float wsum[8];
    __shared__ bool  is_last;
    if ((tid & 31) == 0) wsum[tid >> 5] = lsum;
    __syncthreads();
    if (tid == 0) {
        float v = 0.f;
#pragma unroll
        for (int w = 0; w < 8; w++) v += wsum[w];
        int bi = ((int)blockIdx.z * gridDim.y + blockIdx.y) * gridDim.x
                 + blockIdx.x;
        g_part[bi] = v;
        __threadfence();
        unsigned prev = atomicAdd(&g_count, 1u);
        is_last = (prev == NBLK - 1);
    }
    __syncthreads();

    if (is_last) {
        double s = 0.0;
        for (int i = tid; i < NBLK; i += 256) s += (double)g_part[i];
#pragma unroll
        for (int o = 16; o > 0; o >>= 1)
            s += __shfl_down_sync(0xffffffffu, s, o);
        __shared__ double dsum[8];
        if ((tid & 31) == 0) dsum[tid >> 5] = s;
        __syncthreads();
        if (tid == 0) {
            double tot = 0.0;
#pragma unroll
            for (int w = 0; w < 8; w++) tot += dsum[w];
            out[0] = (float)(1.0 - tot / (2.0 * (double)NPIX));
            g_count = 0;      // reset for next graph replay
        }
    }
}

extern "C" void kernel_launch(void* const* d_in, const int* in_sizes, int n_in,
                              void* d_out, int out_size)
{
    (void)in_sizes; (void)n_in; (void)out_size;
    const float* fused = (const float*)d_in[0];
    const float* imga  = (const float*)d_in[1];
    const float* imgb  = (const float*)d_in[2];

    const size_t smem_bytes = (size_t)(4 * RH * HSTR) * sizeof(u64); // 45.7 KB
    cudaFuncSetAttribute(ssim_kernel,
                         cudaFuncAttributeMaxDynamicSharedMemorySize,
                         (int)smem_bytes);

    dim3 grid(IMG_W / TW, IMG_H / TH, NIMG);
    ssim_kernel<<<grid, 256, smem_bytes>>>(fused, imga, imgb, (float*)d_out);
}

// round 16
// speedup vs baseline: 1.3760x; 1.3760x over previous
#include <cuda_runtime.h>

#define IMG_H 512
#define IMG_W 512
#define NIMG  16
#define TW    32
#define TH    32
#define RH    42            // TH + 10 halo rows of hblur
#define HSTR2 33            // hblur stride in ulonglong2 (16B) units
#define NPIX  (NIMG * IMG_H * IMG_W)
#define NBLK  (NIMG * (IMG_H / TH) * (IMG_W / TW))   // 4096

typedef unsigned long long u64;

__device__ float        g_part[NBLK];
__device__ unsigned int g_count;     // zero-init at load; reset by last block

// ---- packed f32x2 helpers (sm_100+; ptxas never emits these from C++) ----
__device__ __forceinline__ u64 pk(float lo, float hi) {
    u64 r; asm("mov.b64 %0, {%1, %2};" : "=l"(r) : "f"(lo), "f"(hi)); return r;
}
__device__ __forceinline__ void upk(float& lo, float& hi, u64 v) {
    asm("mov.b64 {%0, %1}, %2;" : "=f"(lo), "=f"(hi) : "l"(v));
}
__device__ __forceinline__ u64 fma2(u64 a, u64 b, u64 c) {
    u64 d; asm("fma.rn.f32x2 %0, %1, %2, %3;" : "=l"(d) : "l"(a), "l"(b), "l"(c)); return d;
}

__global__ void __launch_bounds__(256, 4) ssim_kernel(
    const float* __restrict__ fused,
    const float* __restrict__ imga,
    const float* __restrict__ imgb,
    float* __restrict__ out)
{
    // Channel-interleaved hblur (ONLY change vs the 57.9us R6 kernel):
    //   hbA[y][x] = ( pk(muF,muA), pk(muB,eF2) )
    //   hbB[y][x] = ( pk(eA2,eB2), pk(eFA,eFB) )
    extern __shared__ ulonglong2 smem2[];
    ulonglong2* hbA = smem2;                   // [RH][HSTR2]
    ulonglong2* hbB = hbA + RH * HSTR2;        // [RH][HSTR2]

    constexpr float GW[11] = {
        0.00102838f, 0.00759876f, 0.03600077f, 0.10936069f, 0.21300553f,
        0.26601172f,
        0.21300553f, 0.10936069f, 0.03600077f, 0.00759876f, 0.00102838f};
    const float c1 = 0.0001f;
    const float c2 = 0.0009f;

    const int tid = threadIdx.x;
    const int bx  = blockIdx.x;
    const int gy0 = blockIdx.y * TH - 5;
    const size_t base = (size_t)blockIdx.z * (IMG_H * IMG_W);
    const float* fP = fused + base;
    const float* aP = imga + base;
    const float* bP = imgb + base;
    const bool edge_x = (bx == 0) | (bx == (IMG_W / TW) - 1);

    // ---- Stage 1: horizontal blur straight from gmem, 4 outputs/task ----
    // Identical to R6: scalar FFMA-imm accumulation, two thread-passes
    // (256 + 80 tasks); co-resident CTAs cover the tail.
    for (int t = tid; t < RH * 8; t += 256) {
        const int y  = t >> 3;
        const int x0 = (t & 7) * 4;
        const int gy = gy0 + y;

        float acc[4][8];
#pragma unroll
        for (int j = 0; j < 4; j++)
#pragma unroll
            for (int c = 0; c < 8; c++) acc[j][c] = 0.f;

        if (gy >= 0 && gy < IMG_H) {
            if (!edge_x) {
                const int gxa = bx * TW + x0 - 8;       // multiple of 4, >=24
                const float4* f4 = (const float4*)(fP + gy * IMG_W + gxa);
                const float4* a4 = (const float4*)(aP + gy * IMG_W + gxa);
                const float4* b4 = (const float4*)(bP + gy * IMG_W + gxa);
#pragma unroll
                for (int q = 0; q < 5; q++) {
                    float4 fv = f4[q], av = a4[q], bv = b4[q];
                    float fs[4] = {fv.x, fv.y, fv.z, fv.w};
                    float as[4] = {av.x, av.y, av.z, av.w};
                    float bs[4] = {bv.x, bv.y, bv.z, bv.w};
#pragma unroll
                    for (int m = 0; m < 4; m++) {
                        int k = q * 4 + m - 3;          // window px 0..13
                        if (k < 0 || k >= 14) continue;
                        float f = fmaf(fs[m], 0.5f, 0.5f);
                        float a = fmaf(as[m], 0.5f, 0.5f);
                        float b = fmaf(bs[m], 0.5f, 0.5f);
                        float v[8] = {f, a, b, f * f, a * a, b * b,
                                      f * a, f * b};
#pragma unroll
                        for (int j = 0; j < 4; j++) {
                            int tt = k - j;             // compile-time
                            if (tt >= 0 && tt < 11) {
#pragma unroll
                                for (int c = 0; c < 8; c++)
                                    acc[j][c] = fmaf(v[c], GW[tt], acc[j][c]);
                            }
                        }
                    }
                }
            } else {
                const int gxw = bx * TW + x0 - 5;
                const float* frow = fP + gy * IMG_W;
                const float* arow = aP + gy * IMG_W;
                const float* brow = bP + gy * IMG_W;
#pragma unroll
                for (int k = 0; k < 14; k++) {
                    int gx = gxw + k;
                    float f = 0.f, a = 0.f, b = 0.f;
                    if (gx >= 0 && gx < IMG_W) {
                        f = fmaf(frow[gx], 0.5f, 0.5f);
                        a = fmaf(arow[gx], 0.5f, 0.5f);
                        b = fmaf(brow[gx], 0.5f, 0.5f);
                    }
                    float v[8] = {f, a, b, f * f, a * a, b * b, f * a, f * b};
#pragma unroll
                    for (int j = 0; j < 4; j++) {
                        int tt = k - j;
                        if (tt >= 0 && tt < 11) {
#pragma unroll
                            for (int c = 0; c < 8; c++)
                                acc[j][c] = fmaf(v[c], GW[tt], acc[j][c]);
                        }
                    }
                }
            }
        }

        ulonglong2* pA = hbA + y * HSTR2 + x0;
        ulonglong2* pB = hbB + y * HSTR2 + x0;
#pragma unroll
        for (int j = 0; j < 4; j++) {
            pA[j] = make_ulonglong2(pk(acc[j][0], acc[j][1]),
                                    pk(acc[j][2], acc[j][3]));
            pB[j] = make_ulonglong2(pk(acc[j][4], acc[j][5]),
                                    pk(acc[j][6], acc[j][7]));
        }
    }
    __syncthreads();

    // ---- Stage 2: vertical blur (4 outputs/thread) + SSIM ----
    // Identical to R6 except loads: 2x LDS.128 per row instead of 4x LDS.64.
    float lsum = 0.f;
    {
        const int x  = tid & 31;
        const int yb = (tid >> 5) * 4;

        u64 acc[4][4];
#pragma unroll
        for (int j = 0; j < 4; j++)
#pragma unroll
            for (int c = 0; c < 4; c++) acc[j][c] = 0ull;

#pragma unroll
        for (int r = 0; r < 14; r++) {
            ulonglong2 qA = hbA[(yb + r) * HSTR2 + x];
            ulonglong2 qB = hbB[(yb + r) * HSTR2 + x];
#pragma unroll
            for (int j = 0; j < 4; j++) {
                int tt = r - j;
                if (tt >= 0 && tt < 11) {
                    u64 w = pk(GW[tt], GW[tt]);     // imm pair, remat-friendly
                    acc[j][0] = fma2(qA.x, w, acc[j][0]);
                    acc[j][1] = fma2(qA.y, w, acc[j][1]);
                    acc[j][2] = fma2(qB.x, w, acc[j][2]);
                    acc[j][3] = fma2(qB.y, w, acc[j][3]);
                }
            }
        }

#pragma unroll
        for (int j = 0; j < 4; j++) {
            float muF, muA, muB, eF2, eA2, eB2, eFA, eFB;
            upk(muF, muA, acc[j][0]);
            upk(muB, eF2, acc[j][1]);
            upk(eA2, eB2, acc[j][2]);
            upk(eFA, eFB, acc[j][3]);
            float muF2 = muF * muF;
            float sF2  = eF2 - muF2;
            float muA2 = muA * muA;
            float m12a = muF * muA;
            float sA2  = eA2 - muA2;
            float s12a = eFA - m12a;
            float na   = (2.f * m12a + c1) * (2.f * s12a + c2);
            float da   = (muF2 + muA2 + c1) * (sF2 + sA2 + c2);
            float muB2 = muB * muB;
            float m12b = muF * muB;
            float sB2  = eB2 - muB2;
            float s12b = eFB - m12b;
            float nb   = (2.f * m12b + c1) * (2.f * s12b + c2);
            float db   = (muF2 + muB2 + c1) * (sF2 + sB2 + c2);
            float num = fmaf(na, db, nb * da);
            lsum += __fdividef(num, da * db);
        }
    }

    // ---- Block reduction -> deterministic per-block partial ----
#pragma unroll
    for (int o = 16; o > 0; o >>= 1)
        lsum += __shfl_down_sync(0xffffffffu, lsum, o);

    __shared__ float wsum[8];
    __shared__ bool  is_last;
    if ((tid & 31) == 0) wsum[tid >> 5] = lsum;
    __syncthreads();
    if (tid == 0) {
        float v = 0.f;
#pragma unroll
        for (int w = 0; w < 8; w++) v += wsum[w];
        int bi = ((int)blockIdx.z * gridDim.y + blockIdx.y) * gridDim.x
                 + blockIdx.x;
        g_part[bi] = v;
        __threadfence();
        unsigned prev = atomicAdd(&g_count, 1u);
        is_last = (prev == NBLK - 1);
    }
    __syncthreads();

    if (is_last) {
        double s = 0.0;
        for (int i = tid; i < NBLK; i += 256) s += (double)g_part[i];
#pragma unroll
        for (int o = 16; o > 0; o >>= 1)
            s += __shfl_down_sync(0xffffffffu, s, o);
        __shared__ double dsum[8];
        if ((tid & 31) == 0) dsum[tid >> 5] = s;
        __syncthreads();
        if (tid == 0) {
            double tot = 0.0;
#pragma unroll
            for (int w = 0; w < 8; w++) tot += dsum[w];
            out[0] = (float)(1.0 - tot / (2.0 * (double)NPIX));
            g_count = 0;      // reset for next graph replay
        }
    }
}

extern "C" void kernel_launch(void* const* d_in, const int* in_sizes, int n_in,
                              void* d_out, int out_size)
{
    (void)in_sizes; (void)n_in; (void)out_size;
    const float* fused = (const float*)d_in[0];
    const float* imga  = (const float*)d_in[1];
    const float* imgb  = (const float*)d_in[2];

    const size_t smem_bytes = (size_t)(2 * RH * HSTR2) * sizeof(ulonglong2); // 44.4 KB
    cudaFuncSetAttribute(ssim_kernel,
                         cudaFuncAttributeMaxDynamicSharedMemorySize,
                         (int)smem_bytes);

    dim3 grid(IMG_W / TW, IMG_H / TH, NIMG);
    ssim_kernel<<<grid, 256, smem_bytes>>>(fused, imga, imgb, (float*)d_out);
}

// round 17
// speedup vs baseline: 1.5708x; 1.1416x over previous
#include <cuda_runtime.h>

#define IMG_H 512
#define IMG_W 512
#define NIMG  16
#define TW    32
#define TH    32
#define RH    42            // TH + 10 halo rows of hblur
#define HSTR  34            // hblur u64 stride (even -> 16B-aligned px pairs)
#define NPIX  (NIMG * IMG_H * IMG_W)
#define NBLK  (NIMG * (IMG_H / TH) * (IMG_W / TW))   // 4096

typedef unsigned long long u64;

__device__ float        g_part[NBLK];
__device__ unsigned int g_count;     // zero-init at load; reset by last block

// ---- packed f32x2 helpers (sm_100+; ptxas never emits these from C++) ----
__device__ __forceinline__ u64 pk(float lo, float hi) {
    u64 r; asm("mov.b64 %0, {%1, %2};" : "=l"(r) : "f"(lo), "f"(hi)); return r;
}
__device__ __forceinline__ void upk(float& lo, float& hi, u64 v) {
    asm("mov.b64 {%0, %1}, %2;" : "=f"(lo), "=f"(hi) : "l"(v));
}
__device__ __forceinline__ u64 fma2(u64 a, u64 b, u64 c) {
    u64 d; asm("fma.rn.f32x2 %0, %1, %2, %3;" : "=l"(d) : "l"(a), "l"(b), "l"(c)); return d;
}

__global__ void __launch_bounds__(256, 4) ssim_kernel(
    const float* __restrict__ fused,
    const float* __restrict__ imga,
    const float* __restrict__ imgb,
    float* __restrict__ out)
{
    extern __shared__ u64 smem[];
    u64* hb0 = smem;                       // [RH][HSTR] packed (muF, muA)
    u64* hb1 = hb0 + RH * HSTR;            // (muB, eF2)
    u64* hb2 = hb1 + RH * HSTR;            // (eA2, eB2)
    u64* hb3 = hb2 + RH * HSTR;            // (eFA, eFB)

    constexpr float GW[11] = {
        0.00102838f, 0.00759876f, 0.03600077f, 0.10936069f, 0.21300553f,
        0.26601172f,
        0.21300553f, 0.10936069f, 0.03600077f, 0.00759876f, 0.00102838f};
    const float c1 = 0.0001f;
    const float c2 = 0.0009f;

    const int tid = threadIdx.x;
    const int bx  = blockIdx.x;
    const int gy0 = blockIdx.y * TH - 5;
    const size_t base = (size_t)blockIdx.z * (IMG_H * IMG_W);
    const float* fP = fused + base;
    const float* aP = imga + base;
    const float* bP = imgb + base;
    const bool edge_x = (bx == 0) | (bx == (IMG_W / TW) - 1);

    // ---- Stage 1: horizontal blur straight from gmem, 4 outputs/task ----
    // (byte-identical to the 57.9us R6 kernel)
    for (int t = tid; t < RH * 8; t += 256) {
        const int y  = t >> 3;
        const int x0 = (t & 7) * 4;
        const int gy = gy0 + y;

        float acc[4][8];
#pragma unroll
        for (int j = 0; j < 4; j++)
#pragma unroll
            for (int c = 0; c < 8; c++) acc[j][c] = 0.f;

        if (gy >= 0 && gy < IMG_H) {
            if (!edge_x) {
                const int gxa = bx * TW + x0 - 8;       // multiple of 4, >=24
                const float4* f4 = (const float4*)(fP + gy * IMG_W + gxa);
                const float4* a4 = (const float4*)(aP + gy * IMG_W + gxa);
                const float4* b4 = (const float4*)(bP + gy * IMG_W + gxa);
#pragma unroll
                for (int q = 0; q < 5; q++) {
                    float4 fv = f4[q], av = a4[q], bv = b4[q];
                    float fs[4] = {fv.x, fv.y, fv.z, fv.w};
                    float as[4] = {av.x, av.y, av.z, av.w};
                    float bs[4] = {bv.x, bv.y, bv.z, bv.w};
#pragma unroll
                    for (int m = 0; m < 4; m++) {
                        int k = q * 4 + m - 3;          // window px 0..13
                        if (k < 0 || k >= 14) continue;
                        float f = fmaf(fs[m], 0.5f, 0.5f);
                        float a = fmaf(as[m], 0.5f, 0.5f);
                        float b = fmaf(bs[m], 0.5f, 0.5f);
                        float v[8] = {f, a, b, f * f, a * a, b * b,
                                      f * a, f * b};
#pragma unroll
                        for (int j = 0; j < 4; j++) {
                            int tt = k - j;             // compile-time
                            if (tt >= 0 && tt < 11) {
#pragma unroll
                                for (int c = 0; c < 8; c++)
                                    acc[j][c] = fmaf(v[c], GW[tt], acc[j][c]);
                            }
                        }
                    }
                }
            } else {
                const int gxw = bx * TW + x0 - 5;
                const float* frow = fP + gy * IMG_W;
                const float* arow = aP + gy * IMG_W;
                const float* brow = bP + gy * IMG_W;
#pragma unroll
                for (int k = 0; k < 14; k++) {
                    int gx = gxw + k;
                    float f = 0.f, a = 0.f, b = 0.f;
                    if (gx >= 0 && gx < IMG_W) {
                        f = fmaf(frow[gx], 0.5f, 0.5f);
                        a = fmaf(arow[gx], 0.5f, 0.5f);
                        b = fmaf(brow[gx], 0.5f, 0.5f);
                    }
                    float v[8] = {f, a, b, f * f, a * a, b * b, f * a, f * b};
#pragma unroll
                    for (int j = 0; j < 4; j++) {
                        int tt = k - j;
                        if (tt >= 0 && tt < 11) {
#pragma unroll
                            for (int c = 0; c < 8; c++)
                                acc[j][c] = fmaf(v[c], GW[tt], acc[j][c]);
                        }
                    }
                }
            }
        }

        const int o = y * HSTR + x0;        // even -> 16B aligned
        ((ulonglong2*)(hb0 + o))[0] = make_ulonglong2(pk(acc[0][0], acc[0][1]), pk(acc[1][0], acc[1][1]));
        ((ulonglong2*)(hb0 + o))[1] = make_ulonglong2(pk(acc[2][0], acc[2][1]), pk(acc[3][0], acc[3][1]));
        ((ulonglong2*)(hb1 + o))[0] = make_ulonglong2(pk(acc[0][2], acc[0][3]), pk(acc[1][2], acc[1][3]));
        ((ulonglong2*)(hb1 + o))[1] = make_ulonglong2(pk(acc[2][2], acc[2][3]), pk(acc[3][2], acc[3][3]));
        ((ulonglong2*)(hb2 + o))[0] = make_ulonglong2(pk(acc[0][4], acc[0][5]), pk(acc[1][4], acc[1][5]));
        ((ulonglong2*)(hb2 + o))[1] = make_ulonglong2(pk(acc[2][4], acc[2][5]), pk(acc[3][4], acc[3][5]));
        ((ulonglong2*)(hb3 + o))[0] = make_ulonglong2(pk(acc[0][6], acc[0][7]), pk(acc[1][6], acc[1][7]));
        ((ulonglong2*)(hb3 + o))[1] = make_ulonglong2(pk(acc[2][6], acc[2][7]), pk(acc[3][6], acc[3][7]));
    }
    __syncthreads();

    // ---- Stage 2: vertical blur (4 outputs/thread) + SSIM ----
    // ONLY change vs R6: the 11 packed weights are hoisted into W2[] once
    // (22 MOVs) instead of being materialized at every fma2 use site.
    float lsum = 0.f;
    {
        u64 W2[11];
#pragma unroll
        for (int k = 0; k < 11; k++) W2[k] = pk(GW[k], GW[k]);

        const int x  = tid & 31;
        const int yb = (tid >> 5) * 4;

        u64 acc[4][4];
#pragma unroll
        for (int j = 0; j < 4; j++)
#pragma unroll
            for (int c = 0; c < 4; c++) acc[j][c] = 0ull;

#pragma unroll
        for (int r = 0; r < 14; r++) {
            int o = (yb + r) * HSTR + x;
            u64 q0 = hb0[o], q1 = hb1[o], q2 = hb2[o], q3 = hb3[o];
#pragma unroll
            for (int j = 0; j < 4; j++) {
                int tt = r - j;
                if (tt >= 0 && tt < 11) {
                    u64 w = W2[tt];
                    acc[j][0] = fma2(q0, w, acc[j][0]);
                    acc[j][1] = fma2(q1, w, acc[j][1]);
                    acc[j][2] = fma2(q2, w, acc[j][2]);
                    acc[j][3] = fma2(q3, w, acc[j][3]);
                }
            }
        }

#pragma unroll
        for (int j = 0; j < 4; j++) {
            float muF, muA, muB, eF2, eA2, eB2, eFA, eFB;
            upk(muF, muA, acc[j][0]);
            upk(muB, eF2, acc[j][1]);
            upk(eA2, eB2, acc[j][2]);
            upk(eFA, eFB, acc[j][3]);
            float muF2 = muF * muF;
            float sF2  = eF2 - muF2;
            float muA2 = muA * muA;
            float m12a = muF * muA;
            float sA2  = eA2 - muA2;
            float s12a = eFA - m12a;
            float na   = (2.f * m12a + c1) * (2.f * s12a + c2);
            float da   = (muF2 + muA2 + c1) * (sF2 + sA2 + c2);
            float muB2 = muB * muB;
            float m12b = muF * muB;
            float sB2  = eB2 - muB2;
            float s12b = eFB - m12b;
            float nb   = (2.f * m12b + c1) * (2.f * s12b + c2);
            float db   = (muF2 + muB2 + c1) * (sF2 + sB2 + c2);
            float num = fmaf(na, db, nb * da);
            lsum += __fdividef(num, da * db);
        }
    }

    // ---- Block reduction -> deterministic per-block partial ----
#pragma unroll
    for (int o = 16; o > 0; o >>= 1)
        lsum += __shfl_down_sync(0xffffffffu, lsum, o);

    __shared__ float wsum[8];
    __shared__ bool  is_last;
    if ((tid & 31) == 0) wsum[tid >> 5] = lsum;
    __syncthreads();
    if (tid == 0) {
        float v = 0.f;
#pragma unroll
        for (int w = 0; w < 8; w++) v += wsum[w];
        int bi = ((int)blockIdx.z * gridDim.y + blockIdx.y) * gridDim.x
                 + blockIdx.x;
        g_part[bi] = v;
        __threadfence();
        unsigned prev = atomicAdd(&g_count, 1u);
        is_last = (prev == NBLK - 1);
    }
    __syncthreads();

    if (is_last) {
        double s = 0.0;
        for (int i = tid; i < NBLK; i += 256) s += (double)g_part[i];
#pragma unroll
        for (int o = 16; o > 0; o >>= 1)
            s += __shfl_down_sync(0xffffffffu, s, o);
        __shared__ double dsum[8];
        if ((tid & 31) == 0) dsum[tid >> 5] = s;
        __syncthreads();
        if (tid == 0) {
            double tot = 0.0;
#pragma unroll
            for (int w = 0; w < 8; w++) tot += dsum[w];
            out[0] = (float)(1.0 - tot / (2.0 * (double)NPIX));
            g_count = 0;      // reset for next graph replay
        }
    }
}

extern "C" void kernel_launch(void* const* d_in, const int* in_sizes, int n_in,
                              void* d_out, int out_size)
{
    (void)in_sizes; (void)n_in; (void)out_size;
    const float* fused = (const float*)d_in[0];
    const float* imga  = (const float*)d_in[1];
    const float* imgb  = (const float*)d_in[2];

    const size_t smem_bytes = (size_t)(4 * RH * HSTR) * sizeof(u64); // 45.7 KB
    cudaFuncSetAttribute(ssim_kernel,
                         cudaFuncAttributeMaxDynamicSharedMemorySize,
                         (int)smem_bytes);

    dim3 grid(IMG_W / TW, IMG_H / TH, NIMG);
    ssim_kernel<<<grid, 256, smem_bytes>>>(fused, imga, imgb, (float*)d_out);
}